// round 1
// baseline (speedup 1.0000x reference)
#include <cuda_runtime.h>

// Problem-size maxima (from reference: N=50000, E=800000, dims 128/128/64)
#define MAXN 50000
#define MAXE 800000
#define FIN  128
#define FHID 128
#define FOUT2 64

// ---------------- scratch (device globals; no allocation allowed) ----------
__device__ int   g_deg[MAXN];        // degree incl. self loop
__device__ int   g_off[MAXN + 1];    // CSR offsets over edges (excl. self loop)
__device__ int   g_cur[MAXN];        // scatter cursors
__device__ float g_dis[MAXN];        // deg^{-1/2}
__device__ int   g_srcs[MAXE];       // source node per edge, grouped by dest
__device__ int   g_is64;             // edge_index dtype flag
__device__ float g_xw[MAXN * FHID];  // x @ W1
__device__ float g_h [MAXN * FHID];  // relu(agg1 + b1)
__device__ float g_hw[MAXN * FOUT2]; // h @ W2

// ---------------- dtype detection -----------------------------------------
// If edge_index is int32, reinterpreting as int64 packs two values per word:
// high half is a node id (almost surely nonzero) -> value >= 2^32 -> detected.
__global__ void k_detect(const void* ei, int n) {
    const long long* p = (const long long*)ei;
    int tid = threadIdx.x;
    int ok = 1;
    #pragma unroll
    for (int j = 0; j < 8; j++) {
        long long v = p[tid * 8 + j];
        if (v < 0 || v >= (long long)n) ok = 0;
    }
    int all_ok = __syncthreads_and(ok);
    if (tid == 0) g_is64 = all_ok;
}

__device__ __forceinline__ int load_idx(const void* ei, long long pos, int is64) {
    if (is64) return (int)((const long long*)ei)[pos];
    return ((const int*)ei)[pos];
}

// ---------------- degree / normalization ----------------------------------
__global__ void k_init(int n) {
    int i = blockIdx.x * blockDim.x + threadIdx.x;
    if (i < n) { g_deg[i] = 1; g_cur[i] = 0; }  // 1 = self loop
}

__global__ void k_hist(const void* ei, int E) {
    int e = blockIdx.x * blockDim.x + threadIdx.x;
    if (e >= E) return;
    int is64 = g_is64;
    int col = load_idx(ei, (long long)E + e, is64);
    atomicAdd(&g_deg[col], 1);
}

__global__ void k_dis(int n) {
    int i = blockIdx.x * blockDim.x + threadIdx.x;
    if (i < n) g_dis[i] = rsqrtf((float)g_deg[i]);
}

// single-block exclusive scan over (deg[i]-1); writes g_off[0..n]
__global__ void k_scan(int n) {
    __shared__ int sh[1024];
    __shared__ int s_carry;
    int tid = threadIdx.x;
    if (tid == 0) s_carry = 0;
    __syncthreads();
    for (int base = 0; base < n; base += 1024) {
        int c = s_carry;
        int i = base + tid;
        int v = (i < n) ? (g_deg[i] - 1) : 0;
        sh[tid] = v;
        __syncthreads();
        #pragma unroll
        for (int d = 1; d < 1024; d <<= 1) {
            int t = (tid >= d) ? sh[tid - d] : 0;
            __syncthreads();
            sh[tid] += t;
            __syncthreads();
        }
        if (i < n) g_off[i] = c + sh[tid] - v;
        __syncthreads();
        if (tid == 0) s_carry = c + sh[1023];
        __syncthreads();
    }
    if (tid == 0) g_off[n] = s_carry;
}

__global__ void k_scatter(const void* ei, int E) {
    int e = blockIdx.x * blockDim.x + threadIdx.x;
    if (e >= E) return;
    int is64 = g_is64;
    int row = load_idx(ei, e, is64);
    int col = load_idx(ei, (long long)E + e, is64);
    int pos = g_off[col] + atomicAdd(&g_cur[col], 1);
    g_srcs[pos] = row;
}

// ---------------- GEMM: Y[n,FOUT] = X[n,128] @ W[128,FOUT] -----------------
template <int FO>
__global__ void k_gemm(const float* __restrict__ X, const float* __restrict__ W,
                       float* __restrict__ Y, int n) {
    constexpr int CG   = FO / 4;          // col groups of 4
    constexpr int NT   = 512;             // threads per block
    constexpr int ROWS = 4 * NT / CG;     // rows per block (64 or 128)
    constexpr int SXLD = 129;             // padded row stride (bank-conflict-free)
    extern __shared__ float sh[];
    float* sW = sh;                       // 128 * FO
    float* sX = sh + 128 * FO;            // ROWS * SXLD

    int tid  = threadIdx.x;
    int row0 = blockIdx.x * ROWS;

    for (int i = tid; i < 128 * FO; i += NT) sW[i] = W[i];
    for (int i = tid; i < ROWS * 128; i += NT) {
        int r = i >> 7, c = i & 127;
        int gr = row0 + r;
        sX[r * SXLD + c] = (gr < n) ? X[gr * 128 + c] : 0.f;
    }
    __syncthreads();

    int cg = tid % CG;
    int rg = tid / CG;   // handles rows rg*4 .. rg*4+3
    float4 acc[4];
    #pragma unroll
    for (int r = 0; r < 4; r++) acc[r] = make_float4(0.f, 0.f, 0.f, 0.f);

    const float4* sW4 = (const float4*)sW;
    #pragma unroll 4
    for (int k = 0; k < 128; k++) {
        float4 w4 = sW4[k * CG + cg];
        #pragma unroll
        for (int r = 0; r < 4; r++) {
            float a = sX[(rg * 4 + r) * SXLD + k];
            acc[r].x += a * w4.x;
            acc[r].y += a * w4.y;
            acc[r].z += a * w4.z;
            acc[r].w += a * w4.w;
        }
    }
    #pragma unroll
    for (int r = 0; r < 4; r++) {
        int gr = row0 + rg * 4 + r;
        if (gr < n) *(float4*)&Y[gr * FO + cg * 4] = acc[r];
    }
}

// ---------------- aggregation: warp per destination node -------------------
// out[i] = di * sum_{j in in(i)} dis[j]*xw[j]  +  di*di*xw[i]  + b   (opt relu)
__global__ void k_agg128(const float* __restrict__ xw, const float* __restrict__ bias,
                         float* __restrict__ out, int n) {
    int warp = (blockIdx.x * blockDim.x + threadIdx.x) >> 5;
    int lane = threadIdx.x & 31;
    if (warp >= n) return;
    int node = warp;
    int s = g_off[node], e = g_off[node + 1];
    float di = g_dis[node];
    const float4* xw4 = (const float4*)xw;

    float4 acc = make_float4(0.f, 0.f, 0.f, 0.f);
    int p = s;
    for (; p + 1 < e; p += 2) {
        int s0 = g_srcs[p], s1 = g_srcs[p + 1];
        float w0 = g_dis[s0], w1 = g_dis[s1];
        float4 v0 = xw4[s0 * 32 + lane];
        float4 v1 = xw4[s1 * 32 + lane];
        acc.x += w0 * v0.x; acc.y += w0 * v0.y; acc.z += w0 * v0.z; acc.w += w0 * v0.w;
        acc.x += w1 * v1.x; acc.y += w1 * v1.y; acc.z += w1 * v1.z; acc.w += w1 * v1.w;
    }
    if (p < e) {
        int s0 = g_srcs[p];
        float w0 = g_dis[s0];
        float4 v0 = xw4[s0 * 32 + lane];
        acc.x += w0 * v0.x; acc.y += w0 * v0.y; acc.z += w0 * v0.z; acc.w += w0 * v0.w;
    }
    float4 vs = xw4[node * 32 + lane];
    float sw = di * di;
    acc.x = di * acc.x + sw * vs.x;
    acc.y = di * acc.y + sw * vs.y;
    acc.z = di * acc.z + sw * vs.z;
    acc.w = di * acc.w + sw * vs.w;
    float4 bb = ((const float4*)bias)[lane];
    acc.x = fmaxf(acc.x + bb.x, 0.f);
    acc.y = fmaxf(acc.y + bb.y, 0.f);
    acc.z = fmaxf(acc.z + bb.z, 0.f);
    acc.w = fmaxf(acc.w + bb.w, 0.f);
    ((float4*)out)[node * 32 + lane] = acc;
}

__global__ void k_agg64(const float* __restrict__ hw, const float* __restrict__ bias,
                        float* __restrict__ out, int n) {
    int warp = (blockIdx.x * blockDim.x + threadIdx.x) >> 5;
    int lane = threadIdx.x & 31;
    if (warp >= n) return;
    int node = warp;
    int s = g_off[node], e = g_off[node + 1];
    float di = g_dis[node];
    const float2* hw2 = (const float2*)hw;

    float2 acc = make_float2(0.f, 0.f);
    int p = s;
    for (; p + 1 < e; p += 2) {
        int s0 = g_srcs[p], s1 = g_srcs[p + 1];
        float w0 = g_dis[s0], w1 = g_dis[s1];
        float2 v0 = hw2[s0 * 32 + lane];
        float2 v1 = hw2[s1 * 32 + lane];
        acc.x += w0 * v0.x; acc.y += w0 * v0.y;
        acc.x += w1 * v1.x; acc.y += w1 * v1.y;
    }
    if (p < e) {
        int s0 = g_srcs[p];
        float w0 = g_dis[s0];
        float2 v0 = hw2[s0 * 32 + lane];
        acc.x += w0 * v0.x; acc.y += w0 * v0.y;
    }
    float2 vs = hw2[node * 32 + lane];
    float sw = di * di;
    acc.x = di * acc.x + sw * vs.x;
    acc.y = di * acc.y + sw * vs.y;
    float2 bb = ((const float2*)bias)[lane];
    acc.x += bb.x;
    acc.y += bb.y;
    ((float2*)out)[node * 32 + lane] = acc;
}

// ---------------- launch ----------------------------------------------------
extern "C" void kernel_launch(void* const* d_in, const int* in_sizes, int n_in,
                              void* d_out, int out_size) {
    const float* x  = (const float*)d_in[0];
    const void*  ei = d_in[1];
    const float* W1 = (const float*)d_in[2];
    const float* b1 = (const float*)d_in[3];
    const float* W2 = (const float*)d_in[4];
    const float* b2 = (const float*)d_in[5];
    float* out = (float*)d_out;

    int n = in_sizes[0] / FIN;       // 50000
    int E = in_sizes[1] / 2;         // 800000
    if (n > MAXN) n = MAXN;
    if (E > MAXE) E = MAXE;

    // resolve device-global addresses for kernels that take them as args
    float *p_xw, *p_h, *p_hw;
    cudaGetSymbolAddress((void**)&p_xw, g_xw);
    cudaGetSymbolAddress((void**)&p_h,  g_h);
    cudaGetSymbolAddress((void**)&p_hw, g_hw);

    static_assert(sizeof(float4) == 16, "");

    // shared-memory opt-in for the GEMMs (>48KB dynamic)
    size_t sh128 = (size_t)(128 * 128 + 64  * 129) * sizeof(float);   // 98560
    size_t sh64  = (size_t)(128 * 64  + 128 * 129) * sizeof(float);   // 98816
    cudaFuncSetAttribute(k_gemm<128>, cudaFuncAttributeMaxDynamicSharedMemorySize, (int)sh128);
    cudaFuncSetAttribute(k_gemm<64>,  cudaFuncAttributeMaxDynamicSharedMemorySize, (int)sh64);

    // 0) dtype detection (device-side, capture-safe)
    k_detect<<<1, 256>>>(ei, n);

    // 1) degree histogram + normalization + CSR build
    k_init<<<(n + 255) / 256, 256>>>(n);
    k_hist<<<(E + 255) / 256, 256>>>(ei, E);
    k_dis<<<(n + 255) / 256, 256>>>(n);
    k_scan<<<1, 1024>>>(n);
    k_scatter<<<(E + 255) / 256, 256>>>(ei, E);

    // 2) layer 1: xw = x@W1 ; h = relu(agg(xw) + b1)
    k_gemm<128><<<(n + 63) / 64, 512, sh128>>>(x, W1, p_xw, n);
    k_agg128<<<(n + 7) / 8, 256>>>(p_xw, b1, p_h, n);

    // 3) layer 2: hw = h@W2 ; out = agg(hw) + b2
    k_gemm<64><<<(n + 127) / 128, 512, sh64>>>(p_h, W2, p_hw, n);
    k_agg64<<<(n + 7) / 8, 256>>>(p_hw, b2, out, n);
}

// round 2
// speedup vs baseline: 1.4748x; 1.4748x over previous
#include <cuda_runtime.h>

#define MAXN 50000
#define MAXE 800000
#define FIN  128
#define FHID 128
#define FOUT2 64
#define SCAN_TILE 4096
#define MAXTILES 32

// ---------------- scratch (device globals; no allocation allowed) ----------
__device__ int   g_deg[MAXN];
__device__ int   g_off[MAXN + 1];
__device__ int   g_cur[MAXN];
__device__ float g_dis[MAXN];
__device__ int   g_srcs[MAXE];
__device__ int   g_is64;
__device__ int   g_tsum[MAXTILES];
__device__ int   g_toff[MAXTILES];
__device__ float g_xw[MAXN * FHID];
__device__ float g_h [MAXN * FHID];
__device__ float g_hw[MAXN * FOUT2];

// ---------------- init + dtype detection (fused) ---------------------------
// int32 data reinterpreted as int64 packs two ids per word -> high half
// nonzero -> value >= 2^32 -> caught within 2048 samples.
__global__ void k_init_detect(const void* ei, int n) {
    int i = blockIdx.x * blockDim.x + threadIdx.x;
    if (i < n) { g_deg[i] = 1; g_cur[i] = 0; }
    if (blockIdx.x == 0) {
        const long long* p = (const long long*)ei;
        int tid = threadIdx.x;
        int ok = 1;
        #pragma unroll
        for (int j = 0; j < 8; j++) {
            long long v = p[tid * 8 + j];
            if (v < 0 || v >= (long long)n) ok = 0;
        }
        int all_ok = __syncthreads_and(ok);
        if (tid == 0) g_is64 = all_ok;
    }
}

__device__ __forceinline__ int load_idx(const void* ei, long long pos, int is64) {
    if (is64) return (int)((const long long*)ei)[pos];
    return ((const int*)ei)[pos];
}

__global__ void k_hist(const void* ei, int E) {
    int e = blockIdx.x * blockDim.x + threadIdx.x;
    if (e >= E) return;
    int is64 = g_is64;
    int col = load_idx(ei, (long long)E + e, is64);
    atomicAdd(&g_deg[col], 1);
}

// ---------------- 3-phase parallel scan over (deg[i]-1) --------------------
// phase 1: per-tile exclusive scan (1024 thr x 4 elems) + tile sums + g_dis
__global__ void k_scan1(int n) {
    __shared__ int wsum[32];
    int tid  = threadIdx.x;
    int lane = tid & 31, wid = tid >> 5;
    int base = blockIdx.x * SCAN_TILE + tid * 4;

    int v[4];
    #pragma unroll
    for (int j = 0; j < 4; j++) {
        int i = base + j;
        if (i < n) {
            int d = g_deg[i];
            v[j] = d - 1;
            g_dis[i] = rsqrtf((float)d);
        } else v[j] = 0;
    }
    int s = v[0] + v[1] + v[2] + v[3];

    int inc = s;
    #pragma unroll
    for (int d = 1; d < 32; d <<= 1) {
        int t = __shfl_up_sync(0xffffffffu, inc, d);
        if (lane >= d) inc += t;
    }
    if (lane == 31) wsum[wid] = inc;
    __syncthreads();
    if (wid == 0) {
        int w = wsum[lane];
        #pragma unroll
        for (int d = 1; d < 32; d <<= 1) {
            int t = __shfl_up_sync(0xffffffffu, w, d);
            if (lane >= d) w += t;
        }
        wsum[lane] = w;
    }
    __syncthreads();
    int excl = inc - s + (wid > 0 ? wsum[wid - 1] : 0);
    int run = excl;
    #pragma unroll
    for (int j = 0; j < 4; j++) {
        int i = base + j;
        if (i < n) g_off[i] = run;
        run += v[j];
    }
    if (tid == 0) g_tsum[blockIdx.x] = 0;  // ensure defined
    __syncthreads();
    if (tid == 0) g_tsum[blockIdx.x] = wsum[31];
}

// phase 2: one warp scans tile sums, writes tile offsets + grand total
__global__ void k_scan2(int n, int ntiles) {
    int lane = threadIdx.x;
    int t = (lane < ntiles) ? g_tsum[lane] : 0;
    int inc = t;
    #pragma unroll
    for (int d = 1; d < 32; d <<= 1) {
        int u = __shfl_up_sync(0xffffffffu, inc, d);
        if (lane >= d) inc += u;
    }
    if (lane < ntiles) g_toff[lane] = inc - t;
    if (lane == 31) g_off[n] = inc;
}

// phase 3: add tile offsets
__global__ void k_scan3(int n) {
    int i = blockIdx.x * blockDim.x + threadIdx.x;
    if (i < n) g_off[i] += g_toff[i >> 12];
}

__global__ void k_scatter(const void* ei, int E) {
    int e = blockIdx.x * blockDim.x + threadIdx.x;
    if (e >= E) return;
    int is64 = g_is64;
    int row = load_idx(ei, e, is64);
    int col = load_idx(ei, (long long)E + e, is64);
    int pos = g_off[col] + atomicAdd(&g_cur[col], 1);
    g_srcs[pos] = row;
}

// ---------------- GEMM: Y[n,FO] = X[n,128] @ W[128,FO] ---------------------
// 512 threads; each thread computes 8 rows x 4 cols; all SMEM traffic float4.
template <int FO>
__global__ void k_gemm(const float* __restrict__ X, const float* __restrict__ W,
                       float* __restrict__ Y, int n) {
    constexpr int NT   = 512;
    constexpr int CG   = FO / 4;         // 32 or 16
    constexpr int RG   = NT / CG;        // 16 or 32
    constexpr int RPT  = 8;
    constexpr int ROWS = RG * RPT;       // 128 or 256
    constexpr int SXP4 = 33;             // float4 row stride (132 floats)
    extern __shared__ float sh[];
    float4* sW4 = (float4*)sh;                    // 32*FO float4
    float4* sX4 = (float4*)(sh + 128 * FO);       // ROWS * SXP4 float4

    int tid  = threadIdx.x;
    int row0 = blockIdx.x * ROWS;
    const float4* W4g = (const float4*)W;
    const float4* X4g = (const float4*)X;

    for (int i = tid; i < 32 * FO; i += NT) sW4[i] = W4g[i];
    for (int i = tid; i < ROWS * 32; i += NT) {
        int r = i >> 5, c = i & 31;
        int gr = row0 + r;
        sX4[r * SXP4 + c] = (gr < n) ? X4g[gr * 32 + c]
                                     : make_float4(0.f, 0.f, 0.f, 0.f);
    }
    __syncthreads();

    int cg = tid % CG;
    int rb = (tid / CG) * RPT;
    float4 acc[RPT];
    #pragma unroll
    for (int r = 0; r < RPT; r++) acc[r] = make_float4(0.f, 0.f, 0.f, 0.f);

    #pragma unroll 2
    for (int kk = 0; kk < 32; kk++) {
        float4 w0 = sW4[(4 * kk + 0) * CG + cg];
        float4 w1 = sW4[(4 * kk + 1) * CG + cg];
        float4 w2 = sW4[(4 * kk + 2) * CG + cg];
        float4 w3 = sW4[(4 * kk + 3) * CG + cg];
        #pragma unroll
        for (int r = 0; r < RPT; r++) {
            float4 a = sX4[(rb + r) * SXP4 + kk];
            acc[r].x += a.x * w0.x; acc[r].y += a.x * w0.y;
            acc[r].z += a.x * w0.z; acc[r].w += a.x * w0.w;
            acc[r].x += a.y * w1.x; acc[r].y += a.y * w1.y;
            acc[r].z += a.y * w1.z; acc[r].w += a.y * w1.w;
            acc[r].x += a.z * w2.x; acc[r].y += a.z * w2.y;
            acc[r].z += a.z * w2.z; acc[r].w += a.z * w2.w;
            acc[r].x += a.w * w3.x; acc[r].y += a.w * w3.y;
            acc[r].z += a.w * w3.z; acc[r].w += a.w * w3.w;
        }
    }
    float4* Y4 = (float4*)Y;
    #pragma unroll
    for (int r = 0; r < RPT; r++) {
        int gr = row0 + rb + r;
        if (gr < n) Y4[gr * CG + cg] = acc[r];
    }
}

// ---------------- aggregation: warp per destination node -------------------
__global__ void k_agg128(const float* __restrict__ xw, const float* __restrict__ bias,
                         float* __restrict__ out, int n) {
    int warp = (blockIdx.x * blockDim.x + threadIdx.x) >> 5;
    int lane = threadIdx.x & 31;
    if (warp >= n) return;
    int node = warp;
    int s = g_off[node], e = g_off[node + 1];
    float di = g_dis[node];
    const float4* xw4 = (const float4*)xw;

    float4 acc = make_float4(0.f, 0.f, 0.f, 0.f);
    int p = s;
    for (; p + 3 < e; p += 4) {
        int s0 = g_srcs[p], s1 = g_srcs[p + 1], s2 = g_srcs[p + 2], s3 = g_srcs[p + 3];
        float w0 = g_dis[s0], w1 = g_dis[s1], w2 = g_dis[s2], w3 = g_dis[s3];
        float4 v0 = xw4[s0 * 32 + lane];
        float4 v1 = xw4[s1 * 32 + lane];
        float4 v2 = xw4[s2 * 32 + lane];
        float4 v3 = xw4[s3 * 32 + lane];
        acc.x += w0 * v0.x; acc.y += w0 * v0.y; acc.z += w0 * v0.z; acc.w += w0 * v0.w;
        acc.x += w1 * v1.x; acc.y += w1 * v1.y; acc.z += w1 * v1.z; acc.w += w1 * v1.w;
        acc.x += w2 * v2.x; acc.y += w2 * v2.y; acc.z += w2 * v2.z; acc.w += w2 * v2.w;
        acc.x += w3 * v3.x; acc.y += w3 * v3.y; acc.z += w3 * v3.z; acc.w += w3 * v3.w;
    }
    for (; p < e; p++) {
        int s0 = g_srcs[p];
        float w0 = g_dis[s0];
        float4 v0 = xw4[s0 * 32 + lane];
        acc.x += w0 * v0.x; acc.y += w0 * v0.y; acc.z += w0 * v0.z; acc.w += w0 * v0.w;
    }
    float4 vs = xw4[node * 32 + lane];
    float sw = di * di;
    acc.x = di * acc.x + sw * vs.x;
    acc.y = di * acc.y + sw * vs.y;
    acc.z = di * acc.z + sw * vs.z;
    acc.w = di * acc.w + sw * vs.w;
    float4 bb = ((const float4*)bias)[lane];
    acc.x = fmaxf(acc.x + bb.x, 0.f);
    acc.y = fmaxf(acc.y + bb.y, 0.f);
    acc.z = fmaxf(acc.z + bb.z, 0.f);
    acc.w = fmaxf(acc.w + bb.w, 0.f);
    ((float4*)out)[node * 32 + lane] = acc;
}

__global__ void k_agg64(const float* __restrict__ hw, const float* __restrict__ bias,
                        float* __restrict__ out, int n) {
    int warp = (blockIdx.x * blockDim.x + threadIdx.x) >> 5;
    int lane = threadIdx.x & 31;
    if (warp >= n) return;
    int node = warp;
    int s = g_off[node], e = g_off[node + 1];
    float di = g_dis[node];
    const float2* hw2 = (const float2*)hw;

    float2 acc = make_float2(0.f, 0.f);
    int p = s;
    for (; p + 3 < e; p += 4) {
        int s0 = g_srcs[p], s1 = g_srcs[p + 1], s2 = g_srcs[p + 2], s3 = g_srcs[p + 3];
        float w0 = g_dis[s0], w1 = g_dis[s1], w2 = g_dis[s2], w3 = g_dis[s3];
        float2 v0 = hw2[s0 * 32 + lane];
        float2 v1 = hw2[s1 * 32 + lane];
        float2 v2 = hw2[s2 * 32 + lane];
        float2 v3 = hw2[s3 * 32 + lane];
        acc.x += w0 * v0.x; acc.y += w0 * v0.y;
        acc.x += w1 * v1.x; acc.y += w1 * v1.y;
        acc.x += w2 * v2.x; acc.y += w2 * v2.y;
        acc.x += w3 * v3.x; acc.y += w3 * v3.y;
    }
    for (; p < e; p++) {
        int s0 = g_srcs[p];
        float w0 = g_dis[s0];
        float2 v0 = hw2[s0 * 32 + lane];
        acc.x += w0 * v0.x; acc.y += w0 * v0.y;
    }
    float2 vs = hw2[node * 32 + lane];
    float sw = di * di;
    acc.x = di * acc.x + sw * vs.x;
    acc.y = di * acc.y + sw * vs.y;
    float2 bb = ((const float2*)bias)[lane];
    acc.x += bb.x;
    acc.y += bb.y;
    ((float2*)out)[node * 32 + lane] = acc;
}

// ---------------- launch ----------------------------------------------------
extern "C" void kernel_launch(void* const* d_in, const int* in_sizes, int n_in,
                              void* d_out, int out_size) {
    const float* x  = (const float*)d_in[0];
    const void*  ei = d_in[1];
    const float* W1 = (const float*)d_in[2];
    const float* b1 = (const float*)d_in[3];
    const float* W2 = (const float*)d_in[4];
    const float* b2 = (const float*)d_in[5];
    float* out = (float*)d_out;

    int n = in_sizes[0] / FIN;
    int E = in_sizes[1] / 2;
    if (n > MAXN) n = MAXN;
    if (E > MAXE) E = MAXE;
    int ntiles = (n + SCAN_TILE - 1) / SCAN_TILE;

    float *p_xw, *p_h, *p_hw;
    cudaGetSymbolAddress((void**)&p_xw, g_xw);
    cudaGetSymbolAddress((void**)&p_h,  g_h);
    cudaGetSymbolAddress((void**)&p_hw, g_hw);

    size_t sh128 = (size_t)(128 * 128 + 128 * 132) * sizeof(float);   // 133120
    size_t sh64  = (size_t)(128 * 64  + 256 * 132) * sizeof(float);   // 167936
    cudaFuncSetAttribute(k_gemm<128>, cudaFuncAttributeMaxDynamicSharedMemorySize, (int)sh128);
    cudaFuncSetAttribute(k_gemm<64>,  cudaFuncAttributeMaxDynamicSharedMemorySize, (int)sh64);

    // graph preprocessing
    k_init_detect<<<(n + 255) / 256, 256>>>(ei, n);
    k_hist<<<(E + 255) / 256, 256>>>(ei, E);
    k_scan1<<<ntiles, 1024>>>(n);
    k_scan2<<<1, 32>>>(n, ntiles);
    k_scan3<<<(n + 255) / 256, 256>>>(n);
    k_scatter<<<(E + 255) / 256, 256>>>(ei, E);

    // layer 1
    k_gemm<128><<<(n + 127) / 128, 512, sh128>>>(x, W1, p_xw, n);
    k_agg128<<<(n + 7) / 8, 256>>>(p_xw, b1, p_h, n);

    // layer 2
    k_gemm<64><<<(n + 255) / 256, 512, sh64>>>(p_h, W2, p_hw, n);
    k_agg64<<<(n + 7) / 8, 256>>>(p_hw, b2, out, n);
}